// round 1
// baseline (speedup 1.0000x reference)
#include <cuda_runtime.h>

// Problem constants (fixed by the reference):
//   x: [1024, 256] f32, cores: [256, 32, 32] f32,
//   projection: [32, 32, 512] f32, bias: [512] f32, out: [1024, 512] f32.
//
// Math: state ← state @ (x_i * core_i) factors as
//   out[b,o] = s[b] * v[o] + bias[o]
//   s[b] = prod_n x[b,n]
//   u    = ones(32)^T @ core_0 @ ... @ core_255
//   v[o] = sum_{r,l} u[r] * projection[r,l,o]

#define BATCH   1024
#define N_IN    256
#define DD      32
#define OUT_DIM 512
#define CPG     4              // cores per group (parallel pre-product)
#define GROUPS  (N_IN / CPG)   // 64

// Scratch (no allocations allowed -> device globals)
__device__ float g_D[GROUPS * DD * DD];  // 256 KB: group products
__device__ float g_s[BATCH];
__device__ float g_u[DD];
__device__ float g_v[OUT_DIM];

// ---------------------------------------------------------------------------
// K1: blocks [0,64): group matrix products  D_g = core_{4g} @ ... @ core_{4g+3}
//     blocks [64,96): s[b] = prod_n x[b,n]  (one warp per batch row)
// ---------------------------------------------------------------------------
__global__ void __launch_bounds__(1024) k1_groups_and_s(
    const float* __restrict__ x, const float* __restrict__ cores) {
    int tid = threadIdx.x;

    if (blockIdx.x < GROUPS) {
        __shared__ float sA[DD * DD];
        __shared__ float sB[DD * DD];
        int g = blockIdx.x;
        int l = tid >> 5;
        int r = tid & 31;
        const float* cg = cores + (size_t)g * CPG * DD * DD;

        sA[tid] = cg[tid];                 // A = core_{4g}
        float acc = 0.f;
        #pragma unroll
        for (int j = 1; j < CPG; ++j) {
            float c = cg[j * DD * DD + tid];   // prefetch next core
            __syncthreads();                   // prior sA writes + sB reads done
            sB[tid] = c;
            __syncthreads();
            acc = 0.f;
            #pragma unroll
            for (int k = 0; k < DD; ++k)
                acc = fmaf(sA[l * DD + k], sB[k * DD + r], acc);
            if (j < CPG - 1) {
                __syncthreads();
                sA[tid] = acc;
            }
        }
        g_D[g * DD * DD + tid] = acc;
    } else {
        int blk = blockIdx.x - GROUPS;       // 0..31
        if (blk == 0 && tid < OUT_DIM) g_v[tid] = 0.f;  // reset accumulator each replay

        int w = tid >> 5;                    // warp -> batch row within block
        int e = tid & 31;
        int b = blk * 32 + w;
        const float* row = x + (size_t)b * N_IN;
        float p = 1.f;
        #pragma unroll
        for (int i = 0; i < N_IN / 32; ++i) p *= row[e + i * 32];
        #pragma unroll
        for (int off = 16; off; off >>= 1)
            p *= __shfl_xor_sync(0xffffffffu, p, off);
        if (e == 0) g_s[b] = p;
    }
}

// ---------------------------------------------------------------------------
// K2: single warp — sequential vector chain u <- u @ D_g over 64 group matrices
// ---------------------------------------------------------------------------
__device__ __forceinline__ float chain_step(float u, const float* d) {
    float a0 = 0.f, a1 = 0.f, a2 = 0.f, a3 = 0.f;
    #pragma unroll
    for (int k = 0; k < DD; k += 4) {
        a0 = fmaf(__shfl_sync(0xffffffffu, u, k + 0), d[k + 0], a0);
        a1 = fmaf(__shfl_sync(0xffffffffu, u, k + 1), d[k + 1], a1);
        a2 = fmaf(__shfl_sync(0xffffffffu, u, k + 2), d[k + 2], a2);
        a3 = fmaf(__shfl_sync(0xffffffffu, u, k + 3), d[k + 3], a3);
    }
    return (a0 + a1) + (a2 + a3);
}

__global__ void k2_chain() {
    int lane = threadIdx.x;                  // 32 threads
    float u = 1.f;
    float cur[DD], nxt[DD];

    #pragma unroll
    for (int k = 0; k < DD; ++k) cur[k] = g_D[k * DD + lane];

    for (int n = 0; n < GROUPS; n += 2) {
        const float* p1 = g_D + (n + 1) * DD * DD;
        #pragma unroll
        for (int k = 0; k < DD; ++k) nxt[k] = p1[k * DD + lane];

        u = chain_step(u, cur);

        if (n + 2 < GROUPS) {
            const float* p2 = g_D + (n + 2) * DD * DD;
            #pragma unroll
            for (int k = 0; k < DD; ++k) cur[k] = p2[k * DD + lane];
        }
        u = chain_step(u, nxt);
    }
    g_u[lane] = u;
}

// ---------------------------------------------------------------------------
// K3: v[o] = sum_r u[r] * sum_l projection[r,l,o]
//     block p handles r = p (l = 0..31), 512 threads = one o each.
// ---------------------------------------------------------------------------
__global__ void __launch_bounds__(OUT_DIM) k3_v(const float* __restrict__ proj) {
    int o = threadIdx.x;
    int r = blockIdx.x;                      // 32 blocks
    float w = g_u[r];
    const float* base = proj + (size_t)r * DD * OUT_DIM + o;
    float acc = 0.f;
    #pragma unroll
    for (int l = 0; l < DD; ++l)
        acc += base[l * OUT_DIM];
    atomicAdd(&g_v[o], w * acc);
}

// ---------------------------------------------------------------------------
// K4: out[b,o] = s[b] * v[o] + bias[o]   (rank-1 epilogue, float4)
// ---------------------------------------------------------------------------
__global__ void __launch_bounds__(128) k4_out(const float* __restrict__ bias,
                                              float* __restrict__ out) {
    int b = blockIdx.x;                      // 1024 blocks
    int t = threadIdx.x;                     // 128 threads -> 512 floats
    float s = g_s[b];
    float4 v  = reinterpret_cast<const float4*>(g_v)[t];
    float4 bi = reinterpret_cast<const float4*>(bias)[t];
    float4 o;
    o.x = fmaf(s, v.x, bi.x);
    o.y = fmaf(s, v.y, bi.y);
    o.z = fmaf(s, v.z, bi.z);
    o.w = fmaf(s, v.w, bi.w);
    reinterpret_cast<float4*>(out)[(size_t)b * (OUT_DIM / 4) + t] = o;
}

// ---------------------------------------------------------------------------
extern "C" void kernel_launch(void* const* d_in, const int* in_sizes, int n_in,
                              void* d_out, int out_size) {
    const float* x     = (const float*)d_in[0];
    const float* cores = (const float*)d_in[1];
    const float* proj  = (const float*)d_in[2];
    const float* bias  = (const float*)d_in[3];
    float* out = (float*)d_out;

    k1_groups_and_s<<<GROUPS + 32, 1024>>>(x, cores);
    k2_chain<<<1, 32>>>();
    k3_v<<<DD, OUT_DIM>>>(proj);
    k4_out<<<BATCH, 128>>>(bias, out);
}

// round 2
// speedup vs baseline: 1.5777x; 1.5777x over previous
#include <cuda_runtime.h>

// MPSLayer factorization:
//   out[b,o]   = s[b] * v[o] + bias[o]
//   s[b]       = prod_n x[b,n]
//   u          = ones^T @ core_0 @ ... @ core_255   (row vector, len 32)
//   Psum[r,o]  = sum_l proj[r,l,o]                  (input-only, off critical path)
//   v[o]       = sum_r u[r] * Psum[r,o]
//
// Reduction tree for the matrix chain:
//   K1: 64 blocks  -> g_D[g] = core_{4g} @ .. @ core_{4g+3}        (depth 3)
//       128 blocks -> s[b], 64 blocks -> Psum                       (parallel)
//   K2: 8 blocks   -> g_E[e] = g_D[8e] @ .. @ g_D[8e+7]            (depth 7)
//   K3: 1 block    -> u = ones^T @ (g_E[0] .. g_E[7]); v = u^T Psum (depth 8 vec)
//   K4: epilogue   -> out = s ⊗ v + bias

#define BATCH   1024
#define N_IN    256
#define DD      32
#define OUT_DIM 512

__device__ float g_D[64 * DD * DD];    // level-1 products (256 KB)
__device__ float g_E[8 * DD * DD];     // level-2 products (32 KB)
__device__ float g_s[BATCH];
__device__ float g_Psum[DD * OUT_DIM]; // 64 KB
__device__ float g_v[OUT_DIM];

// ---------------------------------------------------------------------------
// Shared 256-thread 32x32x32 matmul step: C = A(smem) @ B(smem), C in regs.
// Thread (l = tid>>3, q = tid&7) computes C[l][4q..4q+3].
// Per warp per k: sA broadcast (4 addrs) + one 128B float4 row slice -> ~2 wf.
// ---------------------------------------------------------------------------
__device__ __forceinline__ float4 mm_step(const float* __restrict__ A,
                                          const float* __restrict__ B,
                                          int l, int q) {
    const float4* B4 = reinterpret_cast<const float4*>(B);
    float4 acc = make_float4(0.f, 0.f, 0.f, 0.f);
    #pragma unroll
    for (int k = 0; k < DD; ++k) {
        float a = A[l * DD + k];
        float4 b = B4[k * 8 + q];
        acc.x = fmaf(a, b.x, acc.x);
        acc.y = fmaf(a, b.y, acc.y);
        acc.z = fmaf(a, b.z, acc.z);
        acc.w = fmaf(a, b.w, acc.w);
    }
    return acc;
}

// Chain NMAT matrices from `src` (global), write product to `dst` (global).
// 256 threads. Ping-pong A buffers + streamed B with one-step LDG prefetch.
template <int NMAT>
__device__ __forceinline__ void mm_chain(const float* __restrict__ src,
                                         float* __restrict__ dst) {
    __shared__ float sM[2][DD * DD];
    __shared__ float sB[DD * DD];
    int tid = threadIdx.x;
    int l = tid >> 3, q = tid & 7;

    const float4* src4 = reinterpret_cast<const float4*>(src);
    reinterpret_cast<float4*>(sM[0])[tid] = src4[tid];           // M0
    reinterpret_cast<float4*>(sB)[tid]    = src4[256 + tid];     // M1
    int cur = 0;
    #pragma unroll
    for (int j = 1; j < NMAT; ++j) {
        float4 nb;
        if (j < NMAT - 1) nb = src4[(j + 1) * 256 + tid];        // prefetch M_{j+1}
        __syncthreads();                                          // A,B visible
        float4 acc = mm_step(sM[cur], sB, l, q);
        __syncthreads();                                          // reads done
        if (j < NMAT - 1) {
            reinterpret_cast<float4*>(sM[cur ^ 1])[tid] = acc;
            reinterpret_cast<float4*>(sB)[tid] = nb;
            cur ^= 1;
        } else {
            reinterpret_cast<float4*>(dst)[tid] = acc;
        }
    }
}

// ---------------------------------------------------------------------------
// K1: blocks [0,64)    : group products of 4 cores
//     blocks [64,192)  : s[b] (8 rows per block, warp per row)
//     blocks [192,256) : Psum[r,o] (block p -> r = p/2, o-half = (p&1)*256)
// ---------------------------------------------------------------------------
__global__ void __launch_bounds__(256) k1_groups_s_psum(
    const float* __restrict__ x, const float* __restrict__ cores,
    const float* __restrict__ proj) {
    int tid = threadIdx.x;
    if (blockIdx.x < 64) {
        int g = blockIdx.x;
        mm_chain<4>(cores + (size_t)g * 4 * DD * DD, g_D + g * DD * DD);
    } else if (blockIdx.x < 192) {
        int blk = blockIdx.x - 64;            // 0..127
        int w = tid >> 5, e = tid & 31;
        int b = blk * 8 + w;
        const float* row = x + (size_t)b * N_IN;
        float p = 1.f;
        #pragma unroll
        for (int i = 0; i < N_IN / DD; ++i) p *= row[e + i * DD];
        #pragma unroll
        for (int off = 16; off; off >>= 1)
            p *= __shfl_xor_sync(0xffffffffu, p, off);
        if (e == 0) g_s[b] = p;
    } else {
        int p = blockIdx.x - 192;             // 0..63
        int r = p >> 1;
        int o = (p & 1) * 256 + tid;
        const float* base = proj + (size_t)r * DD * OUT_DIM + o;
        float acc = 0.f;
        #pragma unroll
        for (int l = 0; l < DD; ++l) acc += base[l * OUT_DIM];
        g_Psum[r * OUT_DIM + o] = acc;
    }
}

// ---------------------------------------------------------------------------
// K2: 8 blocks, each chains 8 of the g_D matrices (depth 7).
// ---------------------------------------------------------------------------
__global__ void __launch_bounds__(256) k2_level2() {
    int e = blockIdx.x;
    mm_chain<8>(g_D + (size_t)e * 8 * DD * DD, g_E + e * DD * DD);
}

// ---------------------------------------------------------------------------
// K3: one block (512 thr). Stage 8 matrices to smem, warp 0 runs the 8-step
// vector chain while Psum is prefetched into registers, then v = u^T Psum.
// ---------------------------------------------------------------------------
__global__ void __launch_bounds__(512) k3_u_v() {
    __shared__ float sE[8 * DD * DD];   // 32 KB
    __shared__ float sU[DD];
    int tid = threadIdx.x;

    // stage g_E (32 KB): 2048 float4 across 512 threads
    const float4* src = reinterpret_cast<const float4*>(g_E);
    float4* dst = reinterpret_cast<float4*>(sE);
    #pragma unroll
    for (int i = 0; i < 4; ++i) dst[tid + i * 512] = src[tid + i * 512];

    // prefetch Psum column `tid` into registers (independent of chain)
    float pcol[DD];
    #pragma unroll
    for (int r = 0; r < DD; ++r) pcol[r] = g_Psum[r * OUT_DIM + tid];

    __syncthreads();

    if (tid < DD) {
        float u = 1.f;
        #pragma unroll
        for (int n = 0; n < 8; ++n) {
            const float* d = sE + n * DD * DD;
            float a0 = 0.f, a1 = 0.f, a2 = 0.f, a3 = 0.f;
            #pragma unroll
            for (int k = 0; k < DD; k += 4) {
                a0 = fmaf(__shfl_sync(0xffffffffu, u, k + 0), d[(k + 0) * DD + tid], a0);
                a1 = fmaf(__shfl_sync(0xffffffffu, u, k + 1), d[(k + 1) * DD + tid], a1);
                a2 = fmaf(__shfl_sync(0xffffffffu, u, k + 2), d[(k + 2) * DD + tid], a2);
                a3 = fmaf(__shfl_sync(0xffffffffu, u, k + 3), d[(k + 3) * DD + tid], a3);
            }
            u = (a0 + a1) + (a2 + a3);
        }
        sU[tid] = u;
    }
    __syncthreads();

    float acc = 0.f;
    #pragma unroll
    for (int r = 0; r < DD; ++r) acc = fmaf(sU[r], pcol[r], acc);
    g_v[tid] = acc;
}

// ---------------------------------------------------------------------------
// K4: out[b,o] = s[b]*v[o] + bias[o]. 64 blocks x 512 thr, 16 rows per block,
// v/bias register-resident, float4 stores.
// ---------------------------------------------------------------------------
__global__ void __launch_bounds__(512) k4_out(const float* __restrict__ bias,
                                              float* __restrict__ out) {
    int tid = threadIdx.x;
    int o4 = tid & 127;          // float4 index within row
    int rq = tid >> 7;           // 0..3 row sub-offset
    float4 v  = reinterpret_cast<const float4*>(g_v)[o4];
    float4 bi = reinterpret_cast<const float4*>(bias)[o4];
    float4* out4 = reinterpret_cast<float4*>(out);
    int base = blockIdx.x * 16;
    #pragma unroll
    for (int i = 0; i < 4; ++i) {
        int b = base + i * 4 + rq;
        float s = g_s[b];
        float4 o;
        o.x = fmaf(s, v.x, bi.x);
        o.y = fmaf(s, v.y, bi.y);
        o.z = fmaf(s, v.z, bi.z);
        o.w = fmaf(s, v.w, bi.w);
        out4[(size_t)b * (OUT_DIM / 4) + o4] = o;
    }
}

// ---------------------------------------------------------------------------
extern "C" void kernel_launch(void* const* d_in, const int* in_sizes, int n_in,
                              void* d_out, int out_size) {
    const float* x     = (const float*)d_in[0];
    const float* cores = (const float*)d_in[1];
    const float* proj  = (const float*)d_in[2];
    const float* bias  = (const float*)d_in[3];
    float* out = (float*)d_out;

    k1_groups_s_psum<<<256, 256>>>(x, cores, proj);
    k2_level2<<<8, 256>>>();
    k3_u_v<<<1, 512>>>();
    k4_out<<<64, 512>>>(bias, out);
}